// round 3
// baseline (speedup 1.0000x reference)
#include <cuda_runtime.h>
#include <cstdint>

#define NNODES 50000
#define NE     800000
#define NET    850000   // NE + NNODES self loops

// ---------------- scratch (device globals; no allocation allowed) ----------
__device__ __align__(16) float    g_xl [NNODES * 128];
__device__ __align__(16) float    g_xr [NNODES * 128];
__device__ __align__(16) float    g_h  [NNODES * 128];
__device__ __align__(16) float    g_acc[NNODES * 128];
__device__ __align__(16) float    g_p  [(size_t)NET * 8];
__device__              unsigned  g_m  [NNODES * 8];
__device__              float     g_s  [NNODES * 8];
__device__              float     g_bn [256];
__device__              int       g_src[NET];
__device__              int       g_dst[NET];
__device__              int       g_is64;

// order-preserving float <-> uint encoding for atomicMax on floats
__device__ __forceinline__ unsigned encf(float f) {
    unsigned u = __float_as_uint(f);
    return (u & 0x80000000u) ? ~u : (u | 0x80000000u);
}
__device__ __forceinline__ float decf(unsigned u) {
    return (u & 0x80000000u) ? __uint_as_float(u ^ 0x80000000u)
                             : __uint_as_float(~u);
}

__global__ void kzero(float* a, int n) {
    int i = blockIdx.x * blockDim.x + threadIdx.x;
    if (i < n) a[i] = 0.f;
}

// ---------------- edge index dtype detection + conversion -------------------
// int64 little-endian: odd 32-bit words are high halves == 0 for node ids.
// int32: odd words are random node ids; all-zero over 64 samples ~ impossible.
__global__ void detect_dtype(const int* __restrict__ ei) {
    int any = 0;
#pragma unroll
    for (int i = 1; i < 128; i += 2) any |= ei[i];
    g_is64 = (any == 0) ? 1 : 0;
}

__global__ void convert_edges(const int* __restrict__ ei,
                              int* __restrict__ src, int* __restrict__ dst) {
    int e = blockIdx.x * blockDim.x + threadIdx.x;
    if (e >= NET) return;
    if (e < NE) {
        if (g_is64) { src[e] = ei[2 * e]; dst[e] = ei[2 * (NE + e)]; }
        else        { src[e] = ei[e];     dst[e] = ei[NE + e]; }
    } else {
        src[e] = dst[e] = e - NE;
    }
}

// ---------------- linear layers --------------------------------------------
// layer 1: in=2 -> out=128 (both l and r sides)
__global__ void lin1(const float* __restrict__ x,
                     const float* __restrict__ Wl, const float* __restrict__ bl,
                     const float* __restrict__ Wr, const float* __restrict__ br,
                     float* __restrict__ xl, float* __restrict__ xr) {
    int i = blockIdx.x * blockDim.x + threadIdx.x;
    if (i >= NNODES * 128) return;
    int n = i >> 7, j = i & 127;
    float x0 = x[2 * n], x1 = x[2 * n + 1];
    xl[i] = x0 * Wl[j] + x1 * Wl[128 + j] + bl[j];
    xr[i] = x0 * Wr[j] + x1 * Wr[128 + j] + br[j];
}

// layer 2: in=128 -> out=64.  4 nodes per 256-thread block, rows staged in smem.
__global__ __launch_bounds__(256) void lin_mid(
        const float* __restrict__ x,
        const float* __restrict__ Wl, const float* __restrict__ bl,
        const float* __restrict__ Wr, const float* __restrict__ br,
        float* __restrict__ xl, float* __restrict__ xr) {
    __shared__ float sx[4][128];
    int node0 = blockIdx.x * 4;
    for (int t = threadIdx.x; t < 512; t += 256) {
        int nn = t >> 7, k = t & 127;
        sx[nn][k] = x[(node0 + nn) * 128 + k];
    }
    __syncthreads();
    int nn = threadIdx.x >> 6;
    int j  = threadIdx.x & 63;
    int n  = node0 + nn;
    float al = bl[j], ar = br[j];
#pragma unroll 8
    for (int k = 0; k < 128; k++) {
        float v = sx[nn][k];
        al += v * Wl[k * 64 + j];
        ar += v * Wr[k * 64 + j];
    }
    xl[n * 64 + j] = al;
    xr[n * 64 + j] = ar;
}

// layer 3: in=64 -> out=2.  warp per node, shuffle reduce.
__global__ void lin3(const float* __restrict__ x,
                     const float* __restrict__ Wl, const float* __restrict__ bl,
                     const float* __restrict__ Wr, const float* __restrict__ br,
                     float* __restrict__ xl, float* __restrict__ xr) {
    int w = (blockIdx.x * blockDim.x + threadIdx.x) >> 5;
    int lane = threadIdx.x & 31;
    if (w >= NNODES) return;
    float2 v = ((const float2*)x)[w * 32 + lane];
    int k = 2 * lane;
    float l0 = v.x * Wl[k * 2 + 0] + v.y * Wl[(k + 1) * 2 + 0];
    float l1 = v.x * Wl[k * 2 + 1] + v.y * Wl[(k + 1) * 2 + 1];
    float r0 = v.x * Wr[k * 2 + 0] + v.y * Wr[(k + 1) * 2 + 0];
    float r1 = v.x * Wr[k * 2 + 1] + v.y * Wr[(k + 1) * 2 + 1];
#pragma unroll
    for (int o = 16; o > 0; o >>= 1) {
        l0 += __shfl_xor_sync(~0u, l0, o);
        l1 += __shfl_xor_sync(~0u, l1, o);
        r0 += __shfl_xor_sync(~0u, r0, o);
        r1 += __shfl_xor_sync(~0u, r1, o);
    }
    if (lane == 0) {
        xl[w * 2 + 0] = l0 + bl[0];
        xl[w * 2 + 1] = l1 + bl[1];
        xr[w * 2 + 0] = r0 + br[0];
        xr[w * 2 + 1] = r1 + br[1];
    }
}

// ---------------- edge passes ----------------------------------------------
// logits + segment max.  warp per edge.  HC = 128 (float4/lane) or 64 (float2/lane)
template <int H, int C>
__global__ __launch_bounds__(256) void edge_logits(
        const int* __restrict__ esrc, const int* __restrict__ edst,
        const float* __restrict__ xl, const float* __restrict__ xr,
        const float* __restrict__ att,
        float* __restrict__ logits, unsigned* __restrict__ mm) {
    constexpr int HC = H * C;
    int w = (blockIdx.x * 256 + threadIdx.x) >> 5;
    int lane = threadIdx.x & 31;
    if (w >= NET) return;
    int s = esrc[w], d = edst[w];
    float part;
    if constexpr (HC == 128) {
        float4 a = ((const float4*)xl)[s * 32 + lane];
        float4 b = ((const float4*)xr)[d * 32 + lane];
        float4 t = ((const float4*)att)[lane];
        float z;
        z = a.x + b.x; z = z > 0.f ? z : 0.2f * z; part  = z * t.x;
        z = a.y + b.y; z = z > 0.f ? z : 0.2f * z; part += z * t.y;
        z = a.z + b.z; z = z > 0.f ? z : 0.2f * z; part += z * t.z;
        z = a.w + b.w; z = z > 0.f ? z : 0.2f * z; part += z * t.w;
        part += __shfl_xor_sync(~0u, part, 1);
        part += __shfl_xor_sync(~0u, part, 2);
        if ((lane & 3) == 0) {
            int h = lane >> 2;
            logits[(size_t)w * H + h] = part;
            atomicMax(&mm[d * H + h], encf(part));
        }
    } else {  // HC == 64
        float2 a = ((const float2*)xl)[s * 32 + lane];
        float2 b = ((const float2*)xr)[d * 32 + lane];
        float2 t = ((const float2*)att)[lane];
        float z;
        z = a.x + b.x; z = z > 0.f ? z : 0.2f * z; part  = z * t.x;
        z = a.y + b.y; z = z > 0.f ? z : 0.2f * z; part += z * t.y;
        part += __shfl_xor_sync(~0u, part, 1);
        part += __shfl_xor_sync(~0u, part, 2);
        part += __shfl_xor_sync(~0u, part, 4);
        if ((lane & 7) == 0) {
            int h = lane >> 3;
            logits[(size_t)w * H + h] = part;
            atomicMax(&mm[d * H + h], encf(part));
        }
    }
}

// layer 3 (H=1, C=2): thread per edge
__global__ void edge_logits3(const int* __restrict__ esrc, const int* __restrict__ edst,
                             const float* __restrict__ xl, const float* __restrict__ xr,
                             const float* __restrict__ att,
                             float* __restrict__ logits, unsigned* __restrict__ mm) {
    int e = blockIdx.x * blockDim.x + threadIdx.x;
    if (e >= NET) return;
    int s = esrc[e], d = edst[e];
    float2 a = ((const float2*)xl)[s];
    float2 b = ((const float2*)xr)[d];
    float z0 = a.x + b.x; z0 = z0 > 0.f ? z0 : 0.2f * z0;
    float z1 = a.y + b.y; z1 = z1 > 0.f ? z1 : 0.2f * z1;
    float lg = z0 * att[0] + z1 * att[1];
    logits[e] = lg;
    atomicMax(&mm[d], encf(lg));
}

// exp(logit - max) + segment sum.  thread per edge.
template <int H>
__global__ void edge_exp(const int* __restrict__ edst,
                         float* __restrict__ p, const unsigned* __restrict__ mm,
                         float* __restrict__ ss) {
    int e = blockIdx.x * blockDim.x + threadIdx.x;
    if (e >= NET) return;
    int d = edst[e];
#pragma unroll
    for (int h = 0; h < H; h++) {
        float m = decf(mm[d * H + h]);
        float v = __expf(p[(size_t)e * H + h] - m);
        p[(size_t)e * H + h] = v;
        atomicAdd(&ss[d * H + h], v);
    }
}

// weighted aggregation.  warp per edge, vector red.global.add.
template <int H, int C>
__global__ __launch_bounds__(256) void edge_agg(
        const int* __restrict__ esrc, const int* __restrict__ edst,
        const float* __restrict__ xl, const float* __restrict__ p,
        const float* __restrict__ ss, float* __restrict__ out) {
    constexpr int HC = H * C;
    int w = (blockIdx.x * 256 + threadIdx.x) >> 5;
    int lane = threadIdx.x & 31;
    if (w >= NET) return;
    int s = esrc[w], d = edst[w];
    float av = 0.f;
    if (lane < H) av = p[(size_t)w * H + lane] / ss[d * H + lane];
    if constexpr (HC == 128) {
        float alpha = __shfl_sync(~0u, av, lane >> 2);
        float4 a = ((const float4*)xl)[s * 32 + lane];
        float4* dst = ((float4*)out) + (d * 32 + lane);
        asm volatile("red.global.add.v4.f32 [%0], {%1,%2,%3,%4};" ::
                     "l"(dst), "f"(a.x * alpha), "f"(a.y * alpha),
                     "f"(a.z * alpha), "f"(a.w * alpha) : "memory");
    } else {
        float alpha = __shfl_sync(~0u, av, lane >> 3);
        float2 a = ((const float2*)xl)[s * 32 + lane];
        float2* dst = ((float2*)out) + (d * 32 + lane);
        asm volatile("red.global.add.v2.f32 [%0], {%1,%2};" ::
                     "l"(dst), "f"(a.x * alpha), "f"(a.y * alpha) : "memory");
    }
}

__global__ void edge_agg3(const int* __restrict__ esrc, const int* __restrict__ edst,
                          const float* __restrict__ xl, const float* __restrict__ p,
                          const float* __restrict__ ss, float* __restrict__ out) {
    int e = blockIdx.x * blockDim.x + threadIdx.x;
    if (e >= NET) return;
    int s = esrc[e], d = edst[e];
    float alpha = p[e] / ss[d];
    float2 a = ((const float2*)xl)[s];
    float2* dst = ((float2*)out) + d;
    asm volatile("red.global.add.v2.f32 [%0], {%1,%2};" ::
                 "l"(dst), "f"(a.x * alpha), "f"(a.y * alpha) : "memory");
}

// ---------------- batchnorm + ELU ------------------------------------------
template <int HC>
__global__ void bn_stats(const float* __restrict__ a, float* __restrict__ bn) {
    int w = (blockIdx.x * blockDim.x + threadIdx.x) >> 5;
    int lane = threadIdx.x & 31;
    int nwarp = (gridDim.x * blockDim.x) >> 5;
    if constexpr (HC == 128) {
        float4 s = {0, 0, 0, 0}, q = {0, 0, 0, 0};
        for (int r = w; r < NNODES; r += nwarp) {
            float4 v = ((const float4*)a)[r * 32 + lane];
            s.x += v.x; s.y += v.y; s.z += v.z; s.w += v.w;
            q.x += v.x * v.x; q.y += v.y * v.y; q.z += v.z * v.z; q.w += v.w * v.w;
        }
        atomicAdd(&bn[lane * 4 + 0], s.x); atomicAdd(&bn[lane * 4 + 1], s.y);
        atomicAdd(&bn[lane * 4 + 2], s.z); atomicAdd(&bn[lane * 4 + 3], s.w);
        atomicAdd(&bn[128 + lane * 4 + 0], q.x); atomicAdd(&bn[128 + lane * 4 + 1], q.y);
        atomicAdd(&bn[128 + lane * 4 + 2], q.z); atomicAdd(&bn[128 + lane * 4 + 3], q.w);
    } else {  // 64
        float2 s = {0, 0}, q = {0, 0};
        for (int r = w; r < NNODES; r += nwarp) {
            float2 v = ((const float2*)a)[r * 32 + lane];
            s.x += v.x; s.y += v.y;
            q.x += v.x * v.x; q.y += v.y * v.y;
        }
        atomicAdd(&bn[lane * 2 + 0], s.x); atomicAdd(&bn[lane * 2 + 1], s.y);
        atomicAdd(&bn[64 + lane * 2 + 0], q.x); atomicAdd(&bn[64 + lane * 2 + 1], q.y);
    }
}

template <int HC>
__global__ void bn_final(float* bn, const float* __restrict__ g,
                         const float* __restrict__ be) {
    int j = threadIdx.x;
    if (j >= HC) return;
    float mean = bn[j] * (1.f / NNODES);
    float var  = bn[HC + j] * (1.f / NNODES) - mean * mean;
    float sc   = g[j] * rsqrtf(var + 1e-5f);
    bn[j]      = sc;
    bn[HC + j] = be[j] - mean * sc;
}

template <int HC>
__global__ void bn_apply(const float* __restrict__ a, const float* __restrict__ bn,
                         float* __restrict__ o) {
    int i = blockIdx.x * blockDim.x + threadIdx.x;
    if (i >= NNODES * HC) return;
    int j = i & (HC - 1);
    float y = a[i] * bn[j] + bn[HC + j];
    o[i] = y > 0.f ? y : expm1f(y);
}

__global__ void finalize(const float* __restrict__ a, const float* __restrict__ bias,
                         float* __restrict__ out) {
    int i = blockIdx.x * blockDim.x + threadIdx.x;
    if (i >= NNODES * 2) return;
    out[i] = a[i] + bias[i & 1];
}

// ---------------- launch ----------------------------------------------------
static inline int cdiv(long long a, long long b) { return (int)((a + b - 1) / b); }

extern "C" void kernel_launch(void* const* d_in, const int* in_sizes, int n_in,
                              void* d_out, int out_size) {
    const float* x  = (const float*)d_in[0];
    const int*   ei = (const int*)d_in[1];   // int32 OR int64; detected on device
    const float *W1l = (const float*)d_in[2],  *b1l = (const float*)d_in[3];
    const float *W1r = (const float*)d_in[4],  *b1r = (const float*)d_in[5];
    const float *a1  = (const float*)d_in[6];
    const float *g1  = (const float*)d_in[8],  *be1 = (const float*)d_in[9];
    const float *W2l = (const float*)d_in[10], *b2l = (const float*)d_in[11];
    const float *W2r = (const float*)d_in[12], *b2r = (const float*)d_in[13];
    const float *a2  = (const float*)d_in[14];
    const float *g2  = (const float*)d_in[16], *be2 = (const float*)d_in[17];
    const float *W3l = (const float*)d_in[18], *b3l = (const float*)d_in[19];
    const float *W3r = (const float*)d_in[20], *b3r = (const float*)d_in[21];
    const float *a3  = (const float*)d_in[22];
    const float *bias3 = (const float*)d_in[23];

    float *xl, *xr, *h, *acc, *p, *s, *bn; unsigned* m; int *esrc, *edst;
    cudaGetSymbolAddress((void**)&xl,   g_xl);
    cudaGetSymbolAddress((void**)&xr,   g_xr);
    cudaGetSymbolAddress((void**)&h,    g_h);
    cudaGetSymbolAddress((void**)&acc,  g_acc);
    cudaGetSymbolAddress((void**)&p,    g_p);
    cudaGetSymbolAddress((void**)&m,    g_m);
    cudaGetSymbolAddress((void**)&s,    g_s);
    cudaGetSymbolAddress((void**)&bn,   g_bn);
    cudaGetSymbolAddress((void**)&esrc, g_src);
    cudaGetSymbolAddress((void**)&edst, g_dst);

    const int T = 256;
    int gW = cdiv((long long)NET * 32, T);   // warp-per-edge grids
    int gE = cdiv(NET, T);                    // thread-per-edge grids

    // ---- edge index normalization (dtype-agnostic) ----
    detect_dtype<<<1, 1>>>(ei);
    convert_edges<<<gE, T>>>(ei, esrc, edst);

    // ---- layer 1: in=2, H=8, C=16 ----
    lin1<<<cdiv(NNODES * 128, T), T>>>(x, W1l, b1l, W1r, b1r, xl, xr);
    kzero<<<cdiv(NNODES * 128, T), T>>>(acc, NNODES * 128);
    kzero<<<cdiv(NNODES * 8, T), T>>>((float*)m, NNODES * 8);
    kzero<<<cdiv(NNODES * 8, T), T>>>(s, NNODES * 8);
    edge_logits<8, 16><<<gW, T>>>(esrc, edst, xl, xr, a1, p, m);
    edge_exp<8><<<gE, T>>>(edst, p, m, s);
    edge_agg<8, 16><<<gW, T>>>(esrc, edst, xl, p, s, acc);
    kzero<<<1, 256>>>(bn, 256);
    bn_stats<128><<<296, T>>>(acc, bn);
    bn_final<128><<<1, 128>>>(bn, g1, be1);
    bn_apply<128><<<cdiv(NNODES * 128, T), T>>>(acc, bn, h);

    // ---- layer 2: in=128, H=4, C=16 ----
    lin_mid<<<NNODES / 4, T>>>(h, W2l, b2l, W2r, b2r, xl, xr);
    kzero<<<cdiv(NNODES * 64, T), T>>>(acc, NNODES * 64);
    kzero<<<cdiv(NNODES * 4, T), T>>>((float*)m, NNODES * 4);
    kzero<<<cdiv(NNODES * 4, T), T>>>(s, NNODES * 4);
    edge_logits<4, 16><<<gW, T>>>(esrc, edst, xl, xr, a2, p, m);
    edge_exp<4><<<gE, T>>>(edst, p, m, s);
    edge_agg<4, 16><<<gW, T>>>(esrc, edst, xl, p, s, acc);
    kzero<<<1, 256>>>(bn, 256);
    bn_stats<64><<<296, T>>>(acc, bn);
    bn_final<64><<<1, 64>>>(bn, g2, be2);
    bn_apply<64><<<cdiv(NNODES * 64, T), T>>>(acc, bn, h);

    // ---- layer 3: in=64, H=1, C=2, mean(=identity for H=1) ----
    lin3<<<cdiv((long long)NNODES * 32, T), T>>>(h, W3l, b3l, W3r, b3r, xl, xr);
    kzero<<<cdiv(NNODES * 2, T), T>>>(acc, NNODES * 2);
    kzero<<<cdiv(NNODES, T), T>>>((float*)m, NNODES);
    kzero<<<cdiv(NNODES, T), T>>>(s, NNODES);
    edge_logits3<<<gE, T>>>(esrc, edst, xl, xr, a3, p, m);
    edge_exp<1><<<gE, T>>>(edst, p, m, s);
    edge_agg3<<<gE, T>>>(esrc, edst, xl, p, s, acc);
    finalize<<<cdiv(NNODES * 2, T), T>>>(acc, bias3, (float*)d_out);
}

// round 4
// speedup vs baseline: 2.1898x; 2.1898x over previous
#include <cuda_runtime.h>
#include <cstdint>

#define NNODES 50000
#define NE     800000
#define NET    850000   // NE + NNODES self loops
#define NSCANB 196      // ceil(50000/256)

// ---------------- scratch (device globals; no allocation allowed) ----------
__device__ __align__(16) float g_xl [NNODES * 128];
__device__ __align__(16) float g_xr [NNODES * 128];
__device__ __align__(16) float g_h  [NNODES * 128];
__device__ __align__(16) float g_acc[NNODES * 128];
__device__ float g_bn [256];
__device__ int   g_src[NET];
__device__ int   g_dst[NET];
__device__ int   g_cnt[NNODES + 1];
__device__ int   g_off[NNODES + 1];
__device__ int   g_woff[NNODES];
__device__ int   g_csr[NET];
__device__ int   g_bsum[256];
__device__ int   g_is64;

__global__ void kzero(float* a, int n) {
    int i = blockIdx.x * blockDim.x + threadIdx.x;
    if (i < n) a[i] = 0.f;
}
__global__ void kzeroi(int* a, int n) {
    int i = blockIdx.x * blockDim.x + threadIdx.x;
    if (i < n) a[i] = 0;
}

// ---------------- edge index dtype detection + conversion -------------------
__global__ void detect_dtype(const int* __restrict__ ei) {
    int any = 0;
#pragma unroll
    for (int i = 1; i < 128; i += 2) any |= ei[i];
    g_is64 = (any == 0) ? 1 : 0;
}

__global__ void convert_edges(const int* __restrict__ ei,
                              int* __restrict__ src, int* __restrict__ dst) {
    int e = blockIdx.x * blockDim.x + threadIdx.x;
    if (e >= NET) return;
    if (e < NE) {
        if (g_is64) { src[e] = ei[2 * e]; dst[e] = ei[2 * (NE + e)]; }
        else        { src[e] = ei[e];     dst[e] = ei[NE + e]; }
    } else {
        src[e] = dst[e] = e - NE;
    }
}

// ---------------- CSR build (count / scan / scatter) ------------------------
__global__ void count_edges(const int* __restrict__ dst, int* __restrict__ cnt) {
    int e = blockIdx.x * blockDim.x + threadIdx.x;
    if (e < NET) atomicAdd(&cnt[dst[e]], 1);
}

__global__ void scan1(const int* __restrict__ cnt, int* __restrict__ excl,
                      int* __restrict__ bsum) {
    __shared__ int sd[256];
    int t = threadIdx.x, i = blockIdx.x * 256 + t;
    int v = (i < NNODES) ? cnt[i] : 0;
    sd[t] = v; __syncthreads();
    for (int o = 1; o < 256; o <<= 1) {
        int x = (t >= o) ? sd[t - o] : 0;
        __syncthreads();
        sd[t] += x;
        __syncthreads();
    }
    if (i < NNODES) excl[i] = sd[t] - v;
    if (t == 255) bsum[blockIdx.x] = sd[255];
}

__global__ void scan2(int* bsum) {
    __shared__ int sd[256];
    int t = threadIdx.x;
    int v = (t < NSCANB) ? bsum[t] : 0;
    sd[t] = v; __syncthreads();
    for (int o = 1; o < 256; o <<= 1) {
        int x = (t >= o) ? sd[t - o] : 0;
        __syncthreads();
        sd[t] += x;
        __syncthreads();
    }
    if (t < NSCANB) bsum[t] = sd[t] - v;   // exclusive
}

__global__ void scan3(int* __restrict__ off, const int* __restrict__ bsum,
                      int* __restrict__ woff) {
    int i = blockIdx.x * 256 + threadIdx.x;
    if (i < NNODES) {
        int o = off[i] + bsum[blockIdx.x];
        off[i] = o; woff[i] = o;
    }
    if (i == 0) off[NNODES] = NET;
}

__global__ void scatter_edges(const int* __restrict__ src, const int* __restrict__ dst,
                              int* __restrict__ woff, int* __restrict__ csr) {
    int e = blockIdx.x * blockDim.x + threadIdx.x;
    if (e < NET) {
        int pos = atomicAdd(&woff[dst[e]], 1);
        csr[pos] = src[e];
    }
}

// ---------------- linear layers --------------------------------------------
// layer 1: in=2 -> out=128
__global__ void lin1(const float* __restrict__ x,
                     const float* __restrict__ Wl, const float* __restrict__ bl,
                     const float* __restrict__ Wr, const float* __restrict__ br,
                     float* __restrict__ xl, float* __restrict__ xr) {
    int i = blockIdx.x * blockDim.x + threadIdx.x;
    if (i >= NNODES * 128) return;
    int n = i >> 7, j = i & 127;
    float x0 = x[2 * n], x1 = x[2 * n + 1];
    xl[i] = x0 * Wl[j] + x1 * Wl[128 + j] + bl[j];
    xr[i] = x0 * Wr[j] + x1 * Wr[128 + j] + br[j];
}

// packed f32x2 helpers (sm_100+)
__device__ __forceinline__ unsigned long long packf2(float lo, float hi) {
    unsigned long long r;
    asm("mov.b64 %0, {%1, %2};" : "=l"(r) : "f"(lo), "f"(hi));
    return r;
}
__device__ __forceinline__ unsigned long long fmaf2(unsigned long long a,
                                                    unsigned long long b,
                                                    unsigned long long c) {
    unsigned long long r;
    asm("fma.rn.f32x2 %0, %1, %2, %3;" : "=l"(r) : "l"(a), "l"(b), "l"(c));
    return r;
}
__device__ __forceinline__ float2 unpackf2(unsigned long long v) {
    float2 o;
    asm("mov.b64 {%0, %1}, %2;" : "=f"(o.x), "=f"(o.y) : "l"(v));
    return o;
}

// layer 2: in=128 -> out=64 (both mats).  64 nodes/block, smem weights,
// 4-node register blocking, packed f32x2 FMA.
__global__ __launch_bounds__(256) void lin_mid2(
        const float* __restrict__ x,
        const float* __restrict__ Wl, const float* __restrict__ bl,
        const float* __restrict__ Wr, const float* __restrict__ br,
        float* __restrict__ xl, float* __restrict__ xr) {
    __shared__ float2 sW[2][128][32];   // 64 KB
    __shared__ float  sxd[16][128];     // 8 KB (16 nodes, direct layout)
    int t = threadIdx.x;
    for (int idx = t; idx < 128 * 32; idx += 256) {
        sW[0][idx >> 5][idx & 31] = ((const float2*)Wl)[idx];
        sW[1][idx >> 5][idx & 31] = ((const float2*)Wr)[idx];
    }
    int nn4 = t >> 6;           // 0..3  (node sub-group)
    int u   = t & 63;
    int mat = u >> 5;           // 0: l, 1: r
    int pr  = u & 31;           // output pair (2 columns)
    int node0 = blockIdx.x * 64;
    unsigned long long bias2;
    {
        float2 bb = mat ? ((const float2*)br)[pr] : ((const float2*)bl)[pr];
        bias2 = packf2(bb.x, bb.y);
    }
    float* dstp = mat ? xr : xl;
    for (int r = 0; r < 4; r++) {
        __syncthreads();
        for (int idx = t; idx < 2048; idx += 256) {
            int nn = idx >> 7, k = idx & 127;
            int node = node0 + r * 16 + nn;
            sxd[nn][k] = (node < NNODES) ? x[node * 128 + k] : 0.f;
        }
        __syncthreads();
        unsigned long long a0 = bias2, a1 = bias2, a2 = bias2, a3 = bias2;
#pragma unroll 4
        for (int k = 0; k < 128; k++) {
            float2 w = sW[mat][k][pr];
            unsigned long long ww = packf2(w.x, w.y);
            float v0 = sxd[nn4 * 4 + 0][k];
            float v1 = sxd[nn4 * 4 + 1][k];
            float v2 = sxd[nn4 * 4 + 2][k];
            float v3 = sxd[nn4 * 4 + 3][k];
            a0 = fmaf2(packf2(v0, v0), ww, a0);
            a1 = fmaf2(packf2(v1, v1), ww, a1);
            a2 = fmaf2(packf2(v2, v2), ww, a2);
            a3 = fmaf2(packf2(v3, v3), ww, a3);
        }
        int nb = node0 + r * 16 + nn4 * 4;
        if (nb + 0 < NNODES) ((float2*)dstp)[(nb + 0) * 32 + pr] = unpackf2(a0);
        if (nb + 1 < NNODES) ((float2*)dstp)[(nb + 1) * 32 + pr] = unpackf2(a1);
        if (nb + 2 < NNODES) ((float2*)dstp)[(nb + 2) * 32 + pr] = unpackf2(a2);
        if (nb + 3 < NNODES) ((float2*)dstp)[(nb + 3) * 32 + pr] = unpackf2(a3);
    }
}

// layer 3: in=64 -> out=2.  warp per node, shuffle reduce.
__global__ void lin3(const float* __restrict__ x,
                     const float* __restrict__ Wl, const float* __restrict__ bl,
                     const float* __restrict__ Wr, const float* __restrict__ br,
                     float* __restrict__ xl, float* __restrict__ xr) {
    int w = (blockIdx.x * blockDim.x + threadIdx.x) >> 5;
    int lane = threadIdx.x & 31;
    if (w >= NNODES) return;
    float2 v = ((const float2*)x)[w * 32 + lane];
    int k = 2 * lane;
    float l0 = v.x * Wl[k * 2 + 0] + v.y * Wl[(k + 1) * 2 + 0];
    float l1 = v.x * Wl[k * 2 + 1] + v.y * Wl[(k + 1) * 2 + 1];
    float r0 = v.x * Wr[k * 2 + 0] + v.y * Wr[(k + 1) * 2 + 0];
    float r1 = v.x * Wr[k * 2 + 1] + v.y * Wr[(k + 1) * 2 + 1];
#pragma unroll
    for (int o = 16; o > 0; o >>= 1) {
        l0 += __shfl_xor_sync(~0u, l0, o);
        l1 += __shfl_xor_sync(~0u, l1, o);
        r0 += __shfl_xor_sync(~0u, r0, o);
        r1 += __shfl_xor_sync(~0u, r1, o);
    }
    if (lane == 0) {
        xl[w * 2 + 0] = l0 + bl[0];
        xl[w * 2 + 1] = l1 + bl[1];
        xr[w * 2 + 0] = r0 + br[0];
        xr[w * 2 + 1] = r1 + br[1];
    }
}

// ---------------- fused GATv2 layer: warp per node, online softmax ----------
template <int H, int C>
__global__ __launch_bounds__(256) void gat_fused(
        const int* __restrict__ off, const int* __restrict__ csr,
        const float* __restrict__ xl, const float* __restrict__ xr,
        const float* __restrict__ att, float* __restrict__ out) {
    constexpr int HC = H * C;
    int w = (blockIdx.x * 256 + threadIdx.x) >> 5;
    int lane = threadIdx.x & 31;
    if (w >= NNODES) return;
    int beg = off[w], end = off[w + 1];
    if constexpr (HC == 128) {
        float4 b = ((const float4*)xr)[w * 32 + lane];
        float4 t = ((const float4*)att)[lane];
        float m = -3.0e38f, ssum = 0.f;
        float4 acc = make_float4(0.f, 0.f, 0.f, 0.f);
        for (int base = beg; base < end; base += 32) {
            int sv = 0;
            if (base + lane < end) sv = csr[base + lane];
            int nl = min(32, end - base);
            for (int k = 0; k < nl; k++) {
                int s = __shfl_sync(~0u, sv, k);
                float4 a = ((const float4*)xl)[s * 32 + lane];
                float z, part;
                z = a.x + b.x; z = fmaxf(z, 0.2f * z); part  = z * t.x;
                z = a.y + b.y; z = fmaxf(z, 0.2f * z); part += z * t.y;
                z = a.z + b.z; z = fmaxf(z, 0.2f * z); part += z * t.z;
                z = a.w + b.w; z = fmaxf(z, 0.2f * z); part += z * t.w;
                part += __shfl_xor_sync(~0u, part, 1);
                part += __shfl_xor_sync(~0u, part, 2);
                float mn = fmaxf(m, part);
                float cs = __expf(m - mn);
                float p  = __expf(part - mn);
                ssum = ssum * cs + p;
                acc.x = acc.x * cs + p * a.x;
                acc.y = acc.y * cs + p * a.y;
                acc.z = acc.z * cs + p * a.z;
                acc.w = acc.w * cs + p * a.w;
                m = mn;
            }
        }
        float inv = 1.f / ssum;
        ((float4*)out)[w * 32 + lane] =
            make_float4(acc.x * inv, acc.y * inv, acc.z * inv, acc.w * inv);
    } else {  // HC == 64
        float2 b = ((const float2*)xr)[w * 32 + lane];
        float2 t = ((const float2*)att)[lane];
        float m = -3.0e38f, ssum = 0.f;
        float2 acc = make_float2(0.f, 0.f);
        for (int base = beg; base < end; base += 32) {
            int sv = 0;
            if (base + lane < end) sv = csr[base + lane];
            int nl = min(32, end - base);
            for (int k = 0; k < nl; k++) {
                int s = __shfl_sync(~0u, sv, k);
                float2 a = ((const float2*)xl)[s * 32 + lane];
                float z, part;
                z = a.x + b.x; z = fmaxf(z, 0.2f * z); part  = z * t.x;
                z = a.y + b.y; z = fmaxf(z, 0.2f * z); part += z * t.y;
                part += __shfl_xor_sync(~0u, part, 1);
                part += __shfl_xor_sync(~0u, part, 2);
                part += __shfl_xor_sync(~0u, part, 4);
                float mn = fmaxf(m, part);
                float cs = __expf(m - mn);
                float p  = __expf(part - mn);
                ssum = ssum * cs + p;
                acc.x = acc.x * cs + p * a.x;
                acc.y = acc.y * cs + p * a.y;
                m = mn;
            }
        }
        float inv = 1.f / ssum;
        ((float2*)out)[w * 32 + lane] = make_float2(acc.x * inv, acc.y * inv);
    }
}

// layer 3 fused: thread per node, H=1 C=2, writes final output (+bias)
__global__ void gat_fused3(const int* __restrict__ off, const int* __restrict__ csr,
                           const float* __restrict__ xl, const float* __restrict__ xr,
                           const float* __restrict__ att, const float* __restrict__ bias,
                           float* __restrict__ out) {
    int d = blockIdx.x * blockDim.x + threadIdx.x;
    if (d >= NNODES) return;
    float2 b = ((const float2*)xr)[d];
    float a0 = att[0], a1 = att[1];
    int beg = off[d], end = off[d + 1];
    float m = -3.0e38f, ssum = 0.f, ac0 = 0.f, ac1 = 0.f;
    for (int j = beg; j < end; j++) {
        int s = csr[j];
        float2 a = ((const float2*)xl)[s];
        float z0 = a.x + b.x; z0 = fmaxf(z0, 0.2f * z0);
        float z1 = a.y + b.y; z1 = fmaxf(z1, 0.2f * z1);
        float lg = z0 * a0 + z1 * a1;
        float mn = fmaxf(m, lg);
        float cs = __expf(m - mn);
        float p  = __expf(lg - mn);
        ssum = ssum * cs + p;
        ac0 = ac0 * cs + p * a.x;
        ac1 = ac1 * cs + p * a.y;
        m = mn;
    }
    out[d * 2 + 0] = ac0 / ssum + bias[0];
    out[d * 2 + 1] = ac1 / ssum + bias[1];
}

// ---------------- batchnorm + ELU ------------------------------------------
template <int HC>
__global__ void bn_stats(const float* __restrict__ a, float* __restrict__ bn) {
    int w = (blockIdx.x * blockDim.x + threadIdx.x) >> 5;
    int lane = threadIdx.x & 31;
    int nwarp = (gridDim.x * blockDim.x) >> 5;
    if constexpr (HC == 128) {
        float4 s = {0, 0, 0, 0}, q = {0, 0, 0, 0};
        for (int r = w; r < NNODES; r += nwarp) {
            float4 v = ((const float4*)a)[r * 32 + lane];
            s.x += v.x; s.y += v.y; s.z += v.z; s.w += v.w;
            q.x += v.x * v.x; q.y += v.y * v.y; q.z += v.z * v.z; q.w += v.w * v.w;
        }
        atomicAdd(&bn[lane * 4 + 0], s.x); atomicAdd(&bn[lane * 4 + 1], s.y);
        atomicAdd(&bn[lane * 4 + 2], s.z); atomicAdd(&bn[lane * 4 + 3], s.w);
        atomicAdd(&bn[128 + lane * 4 + 0], q.x); atomicAdd(&bn[128 + lane * 4 + 1], q.y);
        atomicAdd(&bn[128 + lane * 4 + 2], q.z); atomicAdd(&bn[128 + lane * 4 + 3], q.w);
    } else {
        float2 s = {0, 0}, q = {0, 0};
        for (int r = w; r < NNODES; r += nwarp) {
            float2 v = ((const float2*)a)[r * 32 + lane];
            s.x += v.x; s.y += v.y;
            q.x += v.x * v.x; q.y += v.y * v.y;
        }
        atomicAdd(&bn[lane * 2 + 0], s.x); atomicAdd(&bn[lane * 2 + 1], s.y);
        atomicAdd(&bn[64 + lane * 2 + 0], q.x); atomicAdd(&bn[64 + lane * 2 + 1], q.y);
    }
}

template <int HC>
__global__ void bn_final(float* bn, const float* __restrict__ g,
                         const float* __restrict__ be) {
    int j = threadIdx.x;
    if (j >= HC) return;
    float mean = bn[j] * (1.f / NNODES);
    float var  = bn[HC + j] * (1.f / NNODES) - mean * mean;
    float sc   = g[j] * rsqrtf(var + 1e-5f);
    bn[j]      = sc;
    bn[HC + j] = be[j] - mean * sc;
}

template <int HC>
__global__ void bn_apply(const float* __restrict__ a, const float* __restrict__ bn,
                         float* __restrict__ o) {
    int i = blockIdx.x * blockDim.x + threadIdx.x;
    if (i >= NNODES * HC) return;
    int j = i & (HC - 1);
    float y = a[i] * bn[j] + bn[HC + j];
    o[i] = y > 0.f ? y : expm1f(y);
}

// ---------------- launch ----------------------------------------------------
static inline int cdiv(long long a, long long b) { return (int)((a + b - 1) / b); }

extern "C" void kernel_launch(void* const* d_in, const int* in_sizes, int n_in,
                              void* d_out, int out_size) {
    const float* x  = (const float*)d_in[0];
    const int*   ei = (const int*)d_in[1];   // int32 OR int64; detected on device
    const float *W1l = (const float*)d_in[2],  *b1l = (const float*)d_in[3];
    const float *W1r = (const float*)d_in[4],  *b1r = (const float*)d_in[5];
    const float *a1  = (const float*)d_in[6];
    const float *g1  = (const float*)d_in[8],  *be1 = (const float*)d_in[9];
    const float *W2l = (const float*)d_in[10], *b2l = (const float*)d_in[11];
    const float *W2r = (const float*)d_in[12], *b2r = (const float*)d_in[13];
    const float *a2  = (const float*)d_in[14];
    const float *g2  = (const float*)d_in[16], *be2 = (const float*)d_in[17];
    const float *W3l = (const float*)d_in[18], *b3l = (const float*)d_in[19];
    const float *W3r = (const float*)d_in[20], *b3r = (const float*)d_in[21];
    const float *a3  = (const float*)d_in[22];
    const float *bias3 = (const float*)d_in[23];

    float *xl, *xr, *h, *acc, *bn;
    int *esrc, *edst, *cnt, *off, *woff, *csr, *bsum;
    cudaGetSymbolAddress((void**)&xl,   g_xl);
    cudaGetSymbolAddress((void**)&xr,   g_xr);
    cudaGetSymbolAddress((void**)&h,    g_h);
    cudaGetSymbolAddress((void**)&acc,  g_acc);
    cudaGetSymbolAddress((void**)&bn,   g_bn);
    cudaGetSymbolAddress((void**)&esrc, g_src);
    cudaGetSymbolAddress((void**)&edst, g_dst);
    cudaGetSymbolAddress((void**)&cnt,  g_cnt);
    cudaGetSymbolAddress((void**)&off,  g_off);
    cudaGetSymbolAddress((void**)&woff, g_woff);
    cudaGetSymbolAddress((void**)&csr,  g_csr);
    cudaGetSymbolAddress((void**)&bsum, g_bsum);

    const int T = 256;
    int gE = cdiv(NET, T);                      // thread-per-edge grids
    int gN = cdiv((long long)NNODES * 32, T);   // warp-per-node grids

    // ---- CSR build (dst-sorted adjacency) ----
    detect_dtype<<<1, 1>>>(ei);
    convert_edges<<<gE, T>>>(ei, esrc, edst);
    kzeroi<<<cdiv(NNODES + 1, T), T>>>(cnt, NNODES + 1);
    count_edges<<<gE, T>>>(edst, cnt);
    scan1<<<NSCANB, 256>>>(cnt, off, bsum);
    scan2<<<1, 256>>>(bsum);
    scan3<<<NSCANB, 256>>>(off, bsum, woff);
    scatter_edges<<<gE, T>>>(esrc, edst, woff, csr);

    // ---- layer 1: in=2, H=8, C=16 ----
    lin1<<<cdiv(NNODES * 128, T), T>>>(x, W1l, b1l, W1r, b1r, xl, xr);
    gat_fused<8, 16><<<gN, T>>>(off, csr, xl, xr, a1, acc);
    kzero<<<1, 256>>>(bn, 256);
    bn_stats<128><<<296, T>>>(acc, bn);
    bn_final<128><<<1, 128>>>(bn, g1, be1);
    bn_apply<128><<<cdiv(NNODES * 128, T), T>>>(acc, bn, h);

    // ---- layer 2: in=128, H=4, C=16 ----
    lin_mid2<<<cdiv(NNODES, 64), 256>>>(h, W2l, b2l, W2r, b2r, xl, xr);
    gat_fused<4, 16><<<gN, T>>>(off, csr, xl, xr, a2, acc);
    kzero<<<1, 256>>>(bn, 256);
    bn_stats<64><<<296, T>>>(acc, bn);
    bn_final<64><<<1, 64>>>(bn, g2, be2);
    bn_apply<64><<<cdiv(NNODES * 64, T), T>>>(acc, bn, h);

    // ---- layer 3: in=64, H=1, C=2, fused to output ----
    lin3<<<cdiv((long long)NNODES * 32, T), T>>>(h, W3l, b3l, W3r, b3r, xl, xr);
    gat_fused3<<<cdiv(NNODES, T), T>>>(off, csr, xl, xr, a3, bias3, (float*)d_out);
}

// round 5
// speedup vs baseline: 3.5584x; 1.6249x over previous
#include <cuda_runtime.h>
#include <cstdint>

#define NNODES 50000
#define NE     800000
#define NET    850000   // NE + NNODES self loops
#define NSCANB 196      // ceil(50000/256)

// ---------------- scratch (device globals; no allocation allowed) ----------
__device__ __align__(16) float g_xl [NNODES * 128];
__device__ __align__(16) float g_xr [NNODES * 128];
__device__ __align__(16) float g_acc[NNODES * 128];
__device__ float g_bn [512];            // [0..255] layer1, [256..383] layer2
__device__ int   g_src[NET];
__device__ int   g_dst[NET];
__device__ int   g_cnt[NNODES + 1];
__device__ int   g_off[NNODES + 1];
__device__ int   g_woff[NNODES];
__device__ int   g_csr[NET];
__device__ int   g_bsum[256];

// ---------------- init: zero edge counters + bn accumulators ----------------
__global__ void zero_init(int* __restrict__ cnt, float* __restrict__ bn) {
    int i = blockIdx.x * 256 + threadIdx.x;
    if (i < NNODES + 1) cnt[i] = 0;
    if (i < 512) bn[i] = 0.f;
}

// ---------------- edge conversion + degree count (dtype-agnostic) -----------
__global__ void convert_count(const int* __restrict__ ei,
                              int* __restrict__ src, int* __restrict__ dst,
                              int* __restrict__ cnt) {
    __shared__ int s_is64;
    if (threadIdx.x == 0) {
        int any = 0;
#pragma unroll
        for (int i = 1; i < 128; i += 2) any |= ei[i];
        s_is64 = (any == 0);
    }
    __syncthreads();
    int e = blockIdx.x * blockDim.x + threadIdx.x;
    if (e >= NET) return;
    int s, d;
    if (e < NE) {
        if (s_is64) { s = ei[2 * e]; d = ei[2 * (NE + e)]; }
        else        { s = ei[e];     d = ei[NE + e]; }
    } else {
        s = d = e - NE;
    }
    src[e] = s; dst[e] = d;
    atomicAdd(&cnt[d], 1);
}

// ---------------- CSR build: scan + scatter ---------------------------------
__global__ void scan1(const int* __restrict__ cnt, int* __restrict__ excl,
                      int* __restrict__ bsum) {
    __shared__ int sd[256];
    int t = threadIdx.x, i = blockIdx.x * 256 + t;
    int v = (i < NNODES) ? cnt[i] : 0;
    sd[t] = v; __syncthreads();
    for (int o = 1; o < 256; o <<= 1) {
        int x = (t >= o) ? sd[t - o] : 0;
        __syncthreads();
        sd[t] += x;
        __syncthreads();
    }
    if (i < NNODES) excl[i] = sd[t] - v;
    if (t == 255) bsum[blockIdx.x] = sd[255];
}

__global__ void scan2(int* bsum) {
    __shared__ int sd[256];
    int t = threadIdx.x;
    int v = (t < NSCANB) ? bsum[t] : 0;
    sd[t] = v; __syncthreads();
    for (int o = 1; o < 256; o <<= 1) {
        int x = (t >= o) ? sd[t - o] : 0;
        __syncthreads();
        sd[t] += x;
        __syncthreads();
    }
    if (t < NSCANB) bsum[t] = sd[t] - v;   // exclusive
}

__global__ void scan3(int* __restrict__ off, const int* __restrict__ bsum,
                      int* __restrict__ woff) {
    int i = blockIdx.x * 256 + threadIdx.x;
    if (i < NNODES) {
        int o = off[i] + bsum[blockIdx.x];
        off[i] = o; woff[i] = o;
    }
    if (i == 0) off[NNODES] = NET;
}

__global__ void scatter_edges(const int* __restrict__ src, const int* __restrict__ dst,
                              int* __restrict__ woff, int* __restrict__ csr) {
    int e = blockIdx.x * blockDim.x + threadIdx.x;
    if (e < NET) {
        int pos = atomicAdd(&woff[dst[e]], 1);
        csr[pos] = src[e];
    }
}

// ---------------- layer 1: fully fused (lin + GAT + BN stats) ---------------
// warp per node.  xl/xr rows recomputed from rank-2 inputs; per-lane weights
// live in registers.  x[src] prefetched per 32-edge chunk, broadcast by shfl.
__global__ __launch_bounds__(256) void gat1_fused(
        const int* __restrict__ off, const int* __restrict__ csr,
        const float* __restrict__ x,
        const float* __restrict__ W1l, const float* __restrict__ b1l,
        const float* __restrict__ W1r, const float* __restrict__ b1r,
        const float* __restrict__ att,
        float* __restrict__ out, float* __restrict__ bnacc) {
    __shared__ float sred[256];
    int t = threadIdx.x;
    sred[t] = 0.f;
    __syncthreads();
    int w = (blockIdx.x * 256 + t) >> 5;     // grid exact: 6250 blocks
    int lane = t & 31;
    float4 wl0 = ((const float4*)W1l)[lane];
    float4 wl1 = ((const float4*)(W1l + 128))[lane];
    float4 wr0 = ((const float4*)W1r)[lane];
    float4 wr1 = ((const float4*)(W1r + 128))[lane];
    float4 bl  = ((const float4*)b1l)[lane];
    float4 br  = ((const float4*)b1r)[lane];
    float4 tt  = ((const float4*)att)[lane];
    float2 xd  = ((const float2*)x)[w];
    float4 b;
    b.x = fmaf(xd.x, wr0.x, fmaf(xd.y, wr1.x, br.x));
    b.y = fmaf(xd.x, wr0.y, fmaf(xd.y, wr1.y, br.y));
    b.z = fmaf(xd.x, wr0.z, fmaf(xd.y, wr1.z, br.z));
    b.w = fmaf(xd.x, wr0.w, fmaf(xd.y, wr1.w, br.w));
    int beg = off[w], end = off[w + 1];
    float m = -3.0e38f, ssum = 0.f;
    float4 acc = make_float4(0.f, 0.f, 0.f, 0.f);
    for (int base = beg; base < end; base += 32) {
        int idx = base + lane;
        int sv = (idx < end) ? csr[idx] : 0;
        float2 xs = ((const float2*)x)[sv];
        int nl = min(32, end - base);
        for (int k = 0; k < nl; k++) {
            float x0 = __shfl_sync(~0u, xs.x, k);
            float x1 = __shfl_sync(~0u, xs.y, k);
            float4 a;
            a.x = fmaf(x0, wl0.x, fmaf(x1, wl1.x, bl.x));
            a.y = fmaf(x0, wl0.y, fmaf(x1, wl1.y, bl.y));
            a.z = fmaf(x0, wl0.z, fmaf(x1, wl1.z, bl.z));
            a.w = fmaf(x0, wl0.w, fmaf(x1, wl1.w, bl.w));
            float z, part;
            z = a.x + b.x; z = fmaxf(z, 0.2f * z); part  = z * tt.x;
            z = a.y + b.y; z = fmaxf(z, 0.2f * z); part += z * tt.y;
            z = a.z + b.z; z = fmaxf(z, 0.2f * z); part += z * tt.z;
            z = a.w + b.w; z = fmaxf(z, 0.2f * z); part += z * tt.w;
            part += __shfl_xor_sync(~0u, part, 1);
            part += __shfl_xor_sync(~0u, part, 2);
            float mn = fmaxf(m, part);
            float cs = __expf(m - mn);
            float p  = __expf(part - mn);
            ssum = ssum * cs + p;
            acc.x = acc.x * cs + p * a.x;
            acc.y = acc.y * cs + p * a.y;
            acc.z = acc.z * cs + p * a.z;
            acc.w = acc.w * cs + p * a.w;
            m = mn;
        }
    }
    float inv = 1.f / ssum;
    float4 o = make_float4(acc.x * inv, acc.y * inv, acc.z * inv, acc.w * inv);
    ((float4*)out)[w * 32 + lane] = o;
    // fused BN statistics: block reduction in smem, then global atomics
    int c = 4 * lane;
    atomicAdd(&sred[c + 0], o.x);  atomicAdd(&sred[c + 1], o.y);
    atomicAdd(&sred[c + 2], o.z);  atomicAdd(&sred[c + 3], o.w);
    atomicAdd(&sred[128 + c + 0], o.x * o.x);  atomicAdd(&sred[128 + c + 1], o.y * o.y);
    atomicAdd(&sred[128 + c + 2], o.z * o.z);  atomicAdd(&sred[128 + c + 3], o.w * o.w);
    __syncthreads();
    atomicAdd(&bnacc[t], sred[t]);
}

// ---------------- bn finalize: accumulators -> (scale, shift) ---------------
template <int HC>
__global__ void bn_final(float* bn, const float* __restrict__ g,
                         const float* __restrict__ be) {
    int j = threadIdx.x;
    if (j >= HC) return;
    float mean = bn[j] * (1.f / NNODES);
    float var  = bn[HC + j] * (1.f / NNODES) - mean * mean;
    float sc   = g[j] * rsqrtf(var + 1e-5f);
    bn[j]      = sc;
    bn[HC + j] = be[j] - mean * sc;
}

// packed f32x2 helpers (sm_100+)
__device__ __forceinline__ unsigned long long packf2(float lo, float hi) {
    unsigned long long r;
    asm("mov.b64 %0, {%1, %2};" : "=l"(r) : "f"(lo), "f"(hi));
    return r;
}
__device__ __forceinline__ unsigned long long fmaf2(unsigned long long a,
                                                    unsigned long long b,
                                                    unsigned long long c) {
    unsigned long long r;
    asm("fma.rn.f32x2 %0, %1, %2, %3;" : "=l"(r) : "l"(a), "l"(b), "l"(c));
    return r;
}
__device__ __forceinline__ float2 unpackf2(unsigned long long v) {
    float2 o;
    asm("mov.b64 {%0, %1}, %2;" : "=f"(o.x), "=f"(o.y) : "l"(v));
    return o;
}

// layer 2 linear: reads RAW layer-1 acc, applies BN+ELU on load.  in=128->out=64.
__global__ __launch_bounds__(256) void lin_mid2(
        const float* __restrict__ x, const float* __restrict__ bnp,
        const float* __restrict__ Wl, const float* __restrict__ bl,
        const float* __restrict__ Wr, const float* __restrict__ br,
        float* __restrict__ xl, float* __restrict__ xr) {
    __shared__ float2 sW[2][128][32];   // 64 KB
    __shared__ float  sxd[16][128];     // 8 KB
    int t = threadIdx.x;
    for (int idx = t; idx < 128 * 32; idx += 256) {
        sW[0][idx >> 5][idx & 31] = ((const float2*)Wl)[idx];
        sW[1][idx >> 5][idx & 31] = ((const float2*)Wr)[idx];
    }
    int nn4 = t >> 6;
    int u   = t & 63;
    int mat = u >> 5;
    int pr  = u & 31;
    int node0 = blockIdx.x * 64;
    unsigned long long bias2;
    {
        float2 bb = mat ? ((const float2*)br)[pr] : ((const float2*)bl)[pr];
        bias2 = packf2(bb.x, bb.y);
    }
    float* dstp = mat ? xr : xl;
    for (int r = 0; r < 4; r++) {
        __syncthreads();
        for (int idx = t; idx < 2048; idx += 256) {
            int nn = idx >> 7, k = idx & 127;
            int node = node0 + r * 16 + nn;
            float v = (node < NNODES) ? x[node * 128 + k] : 0.f;
            float y = v * bnp[k] + bnp[128 + k];
            sxd[nn][k] = y > 0.f ? y : expm1f(y);
        }
        __syncthreads();
        unsigned long long a0 = bias2, a1 = bias2, a2 = bias2, a3 = bias2;
#pragma unroll 4
        for (int k = 0; k < 128; k++) {
            float2 wv = sW[mat][k][pr];
            unsigned long long ww = packf2(wv.x, wv.y);
            float v0 = sxd[nn4 * 4 + 0][k];
            float v1 = sxd[nn4 * 4 + 1][k];
            float v2 = sxd[nn4 * 4 + 2][k];
            float v3 = sxd[nn4 * 4 + 3][k];
            a0 = fmaf2(packf2(v0, v0), ww, a0);
            a1 = fmaf2(packf2(v1, v1), ww, a1);
            a2 = fmaf2(packf2(v2, v2), ww, a2);
            a3 = fmaf2(packf2(v3, v3), ww, a3);
        }
        int nb = node0 + r * 16 + nn4 * 4;
        if (nb + 0 < NNODES) ((float2*)dstp)[(nb + 0) * 32 + pr] = unpackf2(a0);
        if (nb + 1 < NNODES) ((float2*)dstp)[(nb + 1) * 32 + pr] = unpackf2(a1);
        if (nb + 2 < NNODES) ((float2*)dstp)[(nb + 2) * 32 + pr] = unpackf2(a2);
        if (nb + 3 < NNODES) ((float2*)dstp)[(nb + 3) * 32 + pr] = unpackf2(a3);
    }
}

// ---------------- layer 2 GAT: warp/node, 4-wide gather, fused BN stats -----
__global__ __launch_bounds__(256) void gat2_fused(
        const int* __restrict__ off, const int* __restrict__ csr,
        const float* __restrict__ xl, const float* __restrict__ xr,
        const float* __restrict__ att,
        float* __restrict__ out, float* __restrict__ bnacc) {
    __shared__ float sred[128];
    int t = threadIdx.x;
    if (t < 128) sred[t] = 0.f;
    __syncthreads();
    int w = (blockIdx.x * 256 + t) >> 5;     // grid exact
    int lane = t & 31;
    float2 b  = ((const float2*)xr)[w * 32 + lane];
    float2 tt = ((const float2*)att)[lane];
    int beg = off[w], end = off[w + 1];
    float m = -3.0e38f, ssum = 0.f;
    float2 acc = make_float2(0.f, 0.f);
    auto upd = [&](float2 a) {
        float z, part;
        z = a.x + b.x; z = fmaxf(z, 0.2f * z); part  = z * tt.x;
        z = a.y + b.y; z = fmaxf(z, 0.2f * z); part += z * tt.y;
        part += __shfl_xor_sync(~0u, part, 1);
        part += __shfl_xor_sync(~0u, part, 2);
        part += __shfl_xor_sync(~0u, part, 4);
        float mn = fmaxf(m, part);
        float cs = __expf(m - mn);
        float p  = __expf(part - mn);
        ssum = ssum * cs + p;
        acc.x = acc.x * cs + p * a.x;
        acc.y = acc.y * cs + p * a.y;
        m = mn;
    };
    for (int base = beg; base < end; base += 32) {
        int idx = base + lane;
        int sv = (idx < end) ? csr[idx] : 0;
        int nl = min(32, end - base);
        int k = 0;
        for (; k + 4 <= nl; k += 4) {
            int s0 = __shfl_sync(~0u, sv, k);
            int s1 = __shfl_sync(~0u, sv, k + 1);
            int s2 = __shfl_sync(~0u, sv, k + 2);
            int s3 = __shfl_sync(~0u, sv, k + 3);
            float2 a0 = ((const float2*)xl)[s0 * 32 + lane];
            float2 a1 = ((const float2*)xl)[s1 * 32 + lane];
            float2 a2 = ((const float2*)xl)[s2 * 32 + lane];
            float2 a3 = ((const float2*)xl)[s3 * 32 + lane];
            upd(a0); upd(a1); upd(a2); upd(a3);
        }
        for (; k < nl; k++) {
            int s = __shfl_sync(~0u, sv, k);
            upd(((const float2*)xl)[s * 32 + lane]);
        }
    }
    float inv = 1.f / ssum;
    float2 o = make_float2(acc.x * inv, acc.y * inv);
    ((float2*)out)[w * 32 + lane] = o;
    int c = 2 * lane;
    atomicAdd(&sred[c + 0], o.x);       atomicAdd(&sred[c + 1], o.y);
    atomicAdd(&sred[64 + c + 0], o.x * o.x); atomicAdd(&sred[64 + c + 1], o.y * o.y);
    __syncthreads();
    if (t < 128) atomicAdd(&bnacc[t], sred[t]);
}

// layer 3 linear: reads RAW layer-2 acc, applies BN+ELU on load.  64 -> 2.
__global__ void lin3(const float* __restrict__ x, const float* __restrict__ bnp,
                     const float* __restrict__ Wl, const float* __restrict__ bl,
                     const float* __restrict__ Wr, const float* __restrict__ br,
                     float* __restrict__ xl, float* __restrict__ xr) {
    int w = (blockIdx.x * blockDim.x + threadIdx.x) >> 5;
    int lane = threadIdx.x & 31;
    if (w >= NNODES) return;
    float2 v = ((const float2*)x)[w * 32 + lane];
    int k = 2 * lane;
    float y0 = v.x * bnp[k] + bnp[64 + k];
    y0 = y0 > 0.f ? y0 : expm1f(y0);
    float y1 = v.y * bnp[k + 1] + bnp[64 + k + 1];
    y1 = y1 > 0.f ? y1 : expm1f(y1);
    float l0 = y0 * Wl[k * 2 + 0] + y1 * Wl[(k + 1) * 2 + 0];
    float l1 = y0 * Wl[k * 2 + 1] + y1 * Wl[(k + 1) * 2 + 1];
    float r0 = y0 * Wr[k * 2 + 0] + y1 * Wr[(k + 1) * 2 + 0];
    float r1 = y0 * Wr[k * 2 + 1] + y1 * Wr[(k + 1) * 2 + 1];
#pragma unroll
    for (int o = 16; o > 0; o >>= 1) {
        l0 += __shfl_xor_sync(~0u, l0, o);
        l1 += __shfl_xor_sync(~0u, l1, o);
        r0 += __shfl_xor_sync(~0u, r0, o);
        r1 += __shfl_xor_sync(~0u, r1, o);
    }
    if (lane == 0) {
        xl[w * 2 + 0] = l0 + bl[0];
        xl[w * 2 + 1] = l1 + bl[1];
        xr[w * 2 + 0] = r0 + br[0];
        xr[w * 2 + 1] = r1 + br[1];
    }
}

// layer 3 GAT: thread per node, writes final output (+bias)
__global__ void gat_fused3(const int* __restrict__ off, const int* __restrict__ csr,
                           const float* __restrict__ xl, const float* __restrict__ xr,
                           const float* __restrict__ att, const float* __restrict__ bias,
                           float* __restrict__ out) {
    int d = blockIdx.x * blockDim.x + threadIdx.x;
    if (d >= NNODES) return;
    float2 b = ((const float2*)xr)[d];
    float a0 = att[0], a1 = att[1];
    int beg = off[d], end = off[d + 1];
    float m = -3.0e38f, ssum = 0.f, ac0 = 0.f, ac1 = 0.f;
    for (int j = beg; j < end; j++) {
        int s = csr[j];
        float2 a = ((const float2*)xl)[s];
        float z0 = a.x + b.x; z0 = fmaxf(z0, 0.2f * z0);
        float z1 = a.y + b.y; z1 = fmaxf(z1, 0.2f * z1);
        float lg = z0 * a0 + z1 * a1;
        float mn = fmaxf(m, lg);
        float cs = __expf(m - mn);
        float p  = __expf(lg - mn);
        ssum = ssum * cs + p;
        ac0 = ac0 * cs + p * a.x;
        ac1 = ac1 * cs + p * a.y;
        m = mn;
    }
    out[d * 2 + 0] = ac0 / ssum + bias[0];
    out[d * 2 + 1] = ac1 / ssum + bias[1];
}

// ---------------- launch ----------------------------------------------------
static inline int cdiv(long long a, long long b) { return (int)((a + b - 1) / b); }

extern "C" void kernel_launch(void* const* d_in, const int* in_sizes, int n_in,
                              void* d_out, int out_size) {
    const float* x  = (const float*)d_in[0];
    const int*   ei = (const int*)d_in[1];   // int32 OR int64; detected on device
    const float *W1l = (const float*)d_in[2],  *b1l = (const float*)d_in[3];
    const float *W1r = (const float*)d_in[4],  *b1r = (const float*)d_in[5];
    const float *a1  = (const float*)d_in[6];
    const float *g1  = (const float*)d_in[8],  *be1 = (const float*)d_in[9];
    const float *W2l = (const float*)d_in[10], *b2l = (const float*)d_in[11];
    const float *W2r = (const float*)d_in[12], *b2r = (const float*)d_in[13];
    const float *a2  = (const float*)d_in[14];
    const float *g2  = (const float*)d_in[16], *be2 = (const float*)d_in[17];
    const float *W3l = (const float*)d_in[18], *b3l = (const float*)d_in[19];
    const float *W3r = (const float*)d_in[20], *b3r = (const float*)d_in[21];
    const float *a3  = (const float*)d_in[22];
    const float *bias3 = (const float*)d_in[23];

    float *xl, *xr, *acc, *bn;
    int *esrc, *edst, *cnt, *off, *woff, *csr, *bsum;
    cudaGetSymbolAddress((void**)&xl,   g_xl);
    cudaGetSymbolAddress((void**)&xr,   g_xr);
    cudaGetSymbolAddress((void**)&acc,  g_acc);
    cudaGetSymbolAddress((void**)&bn,   g_bn);
    cudaGetSymbolAddress((void**)&esrc, g_src);
    cudaGetSymbolAddress((void**)&edst, g_dst);
    cudaGetSymbolAddress((void**)&cnt,  g_cnt);
    cudaGetSymbolAddress((void**)&off,  g_off);
    cudaGetSymbolAddress((void**)&woff, g_woff);
    cudaGetSymbolAddress((void**)&csr,  g_csr);
    cudaGetSymbolAddress((void**)&bsum, g_bsum);

    const int T = 256;
    int gE = cdiv(NET, T);
    int gN = NNODES / 8;   // 6250, exact: warp-per-node grids

    // ---- CSR build ----
    zero_init<<<NSCANB, 256>>>(cnt, bn);
    convert_count<<<gE, T>>>(ei, esrc, edst, cnt);
    scan1<<<NSCANB, 256>>>(cnt, off, bsum);
    scan2<<<1, 256>>>(bsum);
    scan3<<<NSCANB, 256>>>(off, bsum, woff);
    scatter_edges<<<gE, T>>>(esrc, edst, woff, csr);

    // ---- layer 1 (fully fused: lin + GATv2 + BN stats) ----
    gat1_fused<<<gN, T>>>(off, csr, x, W1l, b1l, W1r, b1r, a1, acc, bn);
    bn_final<128><<<1, 128>>>(bn, g1, be1);

    // ---- layer 2 ----
    lin_mid2<<<cdiv(NNODES, 64), 256>>>(acc, bn, W2l, b2l, W2r, b2r, xl, xr);
    gat2_fused<<<gN, T>>>(off, csr, xl, xr, a2, acc, bn + 256);
    bn_final<64><<<1, 64>>>(bn + 256, g2, be2);

    // ---- layer 3 ----
    lin3<<<gN, T>>>(acc, bn + 256, W3l, b3l, W3r, b3r, xl, xr);
    gat_fused3<<<cdiv(NNODES, T), T>>>(off, csr, xl, xr, a3, bias3, (float*)d_out);
}